// round 2
// baseline (speedup 1.0000x reference)
#include <cuda_runtime.h>

typedef unsigned long long ull;

// ---------------------------------------------------------------------------
// Problem constants: B=2048 trees, N=128 nodes, M=127 conv positions.
// Layer channels: 128 -> 256 -> 128 -> 64, then FC 64->32->1.
// ---------------------------------------------------------------------------

// Transposed (and k-major) weights: Wt[(k*C + c)*O + o] = W[o][c][k]
__device__ float g_Wt1[3 * 128 * 256];
__device__ float g_Wt2[3 * 256 * 128];
__device__ float g_Wt3[3 * 128 * 64];

struct SmemT {
    float bufA[256 * 128];   // 128 KB  (big activation buffer)
    float bufB[128 * 128];   //  64 KB  (small activation buffer)
    ull   wbuf[16 * 128];    //  16 KB  (staged weights, pre-duplicated f32x2)
    int   idx[384];          // gather indices for this tree
    float red[80];           // reduction scratch
};

__device__ __forceinline__ ull pk(float lo, float hi) {
    ull r;
    asm("mov.b64 %0, {%1,%2};" : "=l"(r) : "f"(lo), "f"(hi));
    return r;
}
__device__ __forceinline__ void unpk(ull x, float& lo, float& hi) {
    asm("mov.b64 {%0,%1}, %2;" : "=f"(lo), "=f"(hi) : "l"(x));
}
// packed fp32x2 FMA: d = a*b + d (lanewise)
__device__ __forceinline__ void ffma2(ull& d, ull a, ull b) {
    asm("fma.rn.f32x2 %0, %1, %2, %0;" : "+l"(d) : "l"(a), "l"(b));
}

// ---------------------------------------------------------------------------
// One tree-conv layer + per-tree LayerNorm (+ optional leaky ReLU).
//   act_in  : [C][128] in smem
//   act_out : [O][128] in smem
//   Wt      : transposed weights in gmem, [(k*C+c)*O + o]
//   I       : per-thread gather indices I[k*8+j] for positions p = tm*8+j
// Thread map: to = tid>>4 (16 o-groups), tm = tid&15 (16 m-groups of 8).
// ---------------------------------------------------------------------------
template <int C, int O, bool LEAKY>
__device__ void layer(const float* __restrict__ act_in,
                      float* __restrict__ act_out,
                      const float* __restrict__ Wt,
                      const float* __restrict__ bias,
                      SmemT* sm, int tid, const int* I)
{
    constexpr int OT = (O >= 128) ? 128 : O;   // o-tile per pass
    constexpr int RO = OT / 16;                // o's per thread (8 or 4)
    constexpr int PASSES = O / OT;

    const int to = tid >> 4;
    const int tm = tid & 15;

    float lsum = 0.f, lsq = 0.f;

    for (int pass = 0; pass < PASSES; ++pass) {
        const int o_base = pass * OT;

        ull acc[RO][4];
#pragma unroll
        for (int r = 0; r < RO; ++r)
#pragma unroll
            for (int j2 = 0; j2 < 4; ++j2) acc[r][j2] = 0ull;

#pragma unroll
        for (int k = 0; k < 3; ++k) {
            int aa[8];
#pragma unroll
            for (int j = 0; j < 8; ++j) aa[j] = I[k * 8 + j];

            for (int cb = 0; cb < C; cb += 16) {
                __syncthreads();
                // ---- stage 16 reduction rows of weights, duplicated (w,w) ----
                {
                    constexpr int NU = 16 * OT;   // u64 count
#pragma unroll
                    for (int i = 0; i < NU / 256; ++i) {
                        int e = i * 256 + tid;
                        int row = e / OT, o = e % OT;
                        float f = Wt[(k * C + cb + row) * O + o_base + o];
                        sm->wbuf[e] = pk(f, f);
                    }
                }
                __syncthreads();
                // ---- 16 reduction steps ----
#pragma unroll
                for (int s = 0; s < 16; ++s) {
                    const ull* wr = sm->wbuf + s * OT + to * RO;
                    ull w[RO];
#pragma unroll
                    for (int r = 0; r < RO; ++r) w[r] = wr[r];

                    float v[8];
#pragma unroll
                    for (int j = 0; j < 8; ++j) v[j] = act_in[aa[j] + s * 128];

                    ull vp[4];
#pragma unroll
                    for (int j2 = 0; j2 < 4; ++j2) vp[j2] = pk(v[2 * j2], v[2 * j2 + 1]);

#pragma unroll
                    for (int r = 0; r < RO; ++r)
#pragma unroll
                        for (int j2 = 0; j2 < 4; ++j2)
                            ffma2(acc[r][j2], w[r], vp[j2]);
                }
#pragma unroll
                for (int j = 0; j < 8; ++j) aa[j] += 16 * 128;
            }
        }

        // ---- write conv output (+bias), zero slot 0, accumulate LN stats ----
#pragma unroll
        for (int r = 0; r < RO; ++r) {
            const int o = o_base + to * RO + r;
            const float bo = bias[o];
#pragma unroll
            for (int j2 = 0; j2 < 4; ++j2) {
                float x0, x1;
                unpk(acc[r][j2], x0, x1);
                const int p0 = tm * 8 + 2 * j2;
                float y0 = (p0 == 0) ? 0.f : (x0 + bo);
                float y1 = x1 + bo;           // p0+1 is never 0
                act_out[o * 128 + p0]     = y0;
                act_out[o * 128 + p0 + 1] = y1;
                lsum += y0 + y1;
                lsq  += y0 * y0 + y1 * y1;
            }
        }
    }

    // ---- per-tree LayerNorm over all O*128 values (ddof=1 std) ----
#pragma unroll
    for (int off = 16; off; off >>= 1) {
        lsum += __shfl_xor_sync(0xffffffffu, lsum, off);
        lsq  += __shfl_xor_sync(0xffffffffu, lsq,  off);
    }
    const int wid = tid >> 5, lane = tid & 31;
    if (lane == 0) { sm->red[wid] = lsum; sm->red[8 + wid] = lsq; }
    __syncthreads();
    if (tid == 0) {
        float s = 0.f, q = 0.f;
        for (int w = 0; w < 8; ++w) { s += sm->red[w]; q += sm->red[8 + w]; }
        const float n = (float)(O * 128);
        float mean = s / n;
        float var = (q - n * mean * mean) / (n - 1.f);
        var = fmaxf(var, 0.f);
        float inv = 1.f / (sqrtf(var) + 1e-5f);
        sm->red[16] = mean;
        sm->red[17] = inv;
    }
    __syncthreads();
    const float mean = sm->red[16];
    const float inv  = sm->red[17];
    constexpr int E = O * 128 / 256;
    float* pb = act_out + tid * E;
#pragma unroll 4
    for (int i = 0; i < E; ++i) {
        float x = (pb[i] - mean) * inv;
        if (LEAKY && x < 0.f) x *= 0.01f;
        pb[i] = x;
    }
    __syncthreads();
}

// ---------------------------------------------------------------------------
// Weight transpose pre-pass: Wt[(k*C+c)*O + o] = W[o*C*3 + c*3 + k]
// ---------------------------------------------------------------------------
__global__ void wtrans_all(const float* __restrict__ W1,
                           const float* __restrict__ W2,
                           const float* __restrict__ W3)
{
    int i = blockIdx.x * 256 + threadIdx.x;
    if (i < 98304) {                       // W1: O=256, C=128
        const int O = 256, C = 128;
        int o = i % O, t = i / O, c = t % C, k = t / C;
        g_Wt1[i] = W1[(o * C + c) * 3 + k];
    } else if (i < 196608) {               // W2: O=128, C=256
        int j = i - 98304;
        const int O = 128, C = 256;
        int o = j % O, t = j / O, c = t % C, k = t / C;
        g_Wt2[j] = W2[(o * C + c) * 3 + k];
    } else if (i < 221184) {               // W3: O=64, C=128
        int j = i - 196608;
        const int O = 64, C = 128;
        int o = j % O, t = j / O, c = t % C, k = t / C;
        g_Wt3[j] = W3[(o * C + c) * 3 + k];
    }
}

// ---------------------------------------------------------------------------
// Main fused kernel: one CTA per tree.
// ---------------------------------------------------------------------------
__global__ void __launch_bounds__(256, 1)
bao_main(const float* __restrict__ trees,
         const int* __restrict__ indexes,
         const float* __restrict__ b1,
         const float* __restrict__ b2,
         const float* __restrict__ b3,
         const float* __restrict__ W4,
         const float* __restrict__ b4,
         const float* __restrict__ W5,
         const float* __restrict__ b5,
         float* __restrict__ outp)
{
    extern __shared__ char smem_raw[];
    SmemT* sm = (SmemT*)smem_raw;
    const int b = blockIdx.x;
    const int tid = threadIdx.x;

    // load this tree's activations [128][128] into bufB (coalesced float4)
    {
        const float4* src = (const float4*)(trees + (size_t)b * 16384);
        float4* dst = (float4*)sm->bufB;
#pragma unroll
        for (int i = 0; i < 16; ++i) dst[i * 256 + tid] = src[i * 256 + tid];
    }
    // load gather indices (3*127 = 381 ints)
    for (int i = tid; i < 381; i += 256) sm->idx[i] = indexes[(size_t)b * 381 + i];
    __syncthreads();

    // per-thread gather indices for its 8 positions p = tm*8 + j
    const int tm = tid & 15;
    int I[24];
#pragma unroll
    for (int k = 0; k < 3; ++k)
#pragma unroll
        for (int j = 0; j < 8; ++j) {
            int p = tm * 8 + j;
            I[k * 8 + j] = (p == 0) ? 0 : sm->idx[3 * (p - 1) + k];
        }

    layer<128, 256, true >(sm->bufB, sm->bufA, g_Wt1, b1, sm, tid, I);
    layer<256, 128, true >(sm->bufA, sm->bufB, g_Wt2, b2, sm, tid, I);
    layer<128,  64, false>(sm->bufB, sm->bufA, g_Wt3, b3, sm, tid, I);

    // DynamicPooling: max over nodes -> red[0..63]
    if (tid < 64) {
        const float* row = sm->bufA + tid * 128;
        float m = row[0];
#pragma unroll 8
        for (int i = 1; i < 128; ++i) m = fmaxf(m, row[i]);
        sm->red[tid] = m;
    }
    __syncthreads();

    // FC 64->32 (leaky) -> 32->1
    if (tid < 32) {
        float h = b4[tid];
#pragma unroll 8
        for (int j = 0; j < 64; ++j) h += W4[tid * 64 + j] * sm->red[j];
        if (h < 0.f) h *= 0.01f;
        float contrib = W5[tid] * h;
#pragma unroll
        for (int off = 16; off; off >>= 1)
            contrib += __shfl_xor_sync(0xffffffffu, contrib, off);
        if (tid == 0) outp[b] = contrib + b5[0];
    }
}

// ---------------------------------------------------------------------------
// Launch
// ---------------------------------------------------------------------------
extern "C" void kernel_launch(void* const* d_in, const int* in_sizes, int n_in,
                              void* d_out, int out_size)
{
    const float *trees, *W1, *b1, *W2, *b2, *W3, *b3, *W4, *b4, *W5, *b5;
    const int* indexes;

    if (in_sizes[0] == 33554432 && n_in >= 12 && in_sizes[1] == 780288) {
        // setup_inputs dict order: trees, indexes, W1,b1, W2,b2, W3,b3, W4,b4, W5,b5
        trees   = (const float*)d_in[0];
        indexes = (const int*)  d_in[1];
        W1 = (const float*)d_in[2];  b1 = (const float*)d_in[3];
        W2 = (const float*)d_in[4];  b2 = (const float*)d_in[5];
        W3 = (const float*)d_in[6];  b3 = (const float*)d_in[7];
        W4 = (const float*)d_in[8];  b4 = (const float*)d_in[9];
        W5 = (const float*)d_in[10]; b5 = (const float*)d_in[11];
    } else if (in_sizes[0] == 33554432) {
        // reference() arg order: trees, W1,b1, ..., W5,b5, indexes
        trees = (const float*)d_in[0];
        W1 = (const float*)d_in[1];  b1 = (const float*)d_in[2];
        W2 = (const float*)d_in[3];  b2 = (const float*)d_in[4];
        W3 = (const float*)d_in[5];  b3 = (const float*)d_in[6];
        W4 = (const float*)d_in[7];  b4 = (const float*)d_in[8];
        W5 = (const float*)d_in[9];  b5 = (const float*)d_in[10];
        indexes = (const int*)d_in[11];
    } else {
        // alphabetical order: W1..W5, b1..b5, indexes, trees
        W1 = (const float*)d_in[0];  W2 = (const float*)d_in[1];
        W3 = (const float*)d_in[2];  W4 = (const float*)d_in[3];
        W5 = (const float*)d_in[4];
        b1 = (const float*)d_in[5];  b2 = (const float*)d_in[6];
        b3 = (const float*)d_in[7];  b4 = (const float*)d_in[8];
        b5 = (const float*)d_in[9];
        indexes = (const int*)  d_in[10];
        trees   = (const float*)d_in[11];
    }

    // 1) transpose weights into k-major, o-contiguous layout
    wtrans_all<<<(221184 + 255) / 256, 256>>>(W1, W2, W3);

    // 2) fused per-tree pipeline
    const int smem_bytes = (int)sizeof(SmemT);
    cudaFuncSetAttribute(bao_main, cudaFuncAttributeMaxDynamicSharedMemorySize,
                         smem_bytes);
    bao_main<<<2048, 256, smem_bytes>>>(trees, indexes, b1, b2, b3,
                                        W4, b4, W5, b5, (float*)d_out);
}

// round 3
// speedup vs baseline: 1.0001x; 1.0001x over previous
#include <cuda_runtime.h>

typedef unsigned long long ull;

// ---------------------------------------------------------------------------
// Problem constants: B=2048 trees, N=128 nodes, M=127 conv positions.
// Layer channels: 128 -> 256 -> 128 -> 64, then FC 64->32->1.
// ---------------------------------------------------------------------------

// Transposed (and k-major) weights: Wt[(k*C + c)*O + o] = W[o][c][k]
__device__ float g_Wt1[3 * 128 * 256];
__device__ float g_Wt2[3 * 256 * 128];
__device__ float g_Wt3[3 * 128 * 64];

struct SmemT {
    float bufA[256 * 128];   // 128 KB  (big activation buffer)
    float bufB[128 * 128];   //  64 KB  (small activation buffer)
    ull   wbuf[16 * 128];    //  16 KB  (staged weights, pre-duplicated f32x2)
    int   idx[384];          // gather indices for this tree
    float red[80];           // reduction scratch
};

__device__ __forceinline__ ull pk(float lo, float hi) {
    ull r;
    asm("mov.b64 %0, {%1,%2};" : "=l"(r) : "f"(lo), "f"(hi));
    return r;
}
__device__ __forceinline__ void unpk(ull x, float& lo, float& hi) {
    asm("mov.b64 {%0,%1}, %2;" : "=f"(lo), "=f"(hi) : "l"(x));
}
// packed fp32x2 FMA: d = a*b + d (lanewise)
__device__ __forceinline__ void ffma2(ull& d, ull a, ull b) {
    asm("fma.rn.f32x2 %0, %1, %2, %0;" : "+l"(d) : "l"(a), "l"(b));
}

// ---------------------------------------------------------------------------
// One tree-conv layer + per-tree LayerNorm (+ optional leaky ReLU).
//   act_in  : [C][128] in smem
//   act_out : [O][128] in smem
//   Wt      : transposed weights in gmem, [(k*C+c)*O + o]
//   I       : per-thread gather indices I[k*8+j] for positions p = tm*8+j
// Thread map: to = tid>>4 (16 o-groups), tm = tid&15 (16 m-groups of 8).
// ---------------------------------------------------------------------------
template <int C, int O, bool LEAKY>
__device__ void layer(const float* __restrict__ act_in,
                      float* __restrict__ act_out,
                      const float* __restrict__ Wt,
                      const float* __restrict__ bias,
                      SmemT* sm, int tid, const int* I)
{
    constexpr int OT = (O >= 128) ? 128 : O;   // o-tile per pass
    constexpr int RO = OT / 16;                // o's per thread (8 or 4)
    constexpr int PASSES = O / OT;

    const int to = tid >> 4;
    const int tm = tid & 15;

    float lsum = 0.f, lsq = 0.f;

    for (int pass = 0; pass < PASSES; ++pass) {
        const int o_base = pass * OT;

        ull acc[RO][4];
#pragma unroll
        for (int r = 0; r < RO; ++r)
#pragma unroll
            for (int j2 = 0; j2 < 4; ++j2) acc[r][j2] = 0ull;

#pragma unroll
        for (int k = 0; k < 3; ++k) {
            int aa[8];
#pragma unroll
            for (int j = 0; j < 8; ++j) aa[j] = I[k * 8 + j];

            for (int cb = 0; cb < C; cb += 16) {
                __syncthreads();
                // ---- stage 16 reduction rows of weights, duplicated (w,w) ----
                {
                    constexpr int NU = 16 * OT;   // u64 count
#pragma unroll
                    for (int i = 0; i < NU / 256; ++i) {
                        int e = i * 256 + tid;
                        int row = e / OT, o = e % OT;
                        float f = Wt[(k * C + cb + row) * O + o_base + o];
                        sm->wbuf[e] = pk(f, f);
                    }
                }
                __syncthreads();
                // ---- 16 reduction steps ----
#pragma unroll
                for (int s = 0; s < 16; ++s) {
                    const ull* wr = sm->wbuf + s * OT + to * RO;
                    ull w[RO];
#pragma unroll
                    for (int r = 0; r < RO; ++r) w[r] = wr[r];

                    float v[8];
#pragma unroll
                    for (int j = 0; j < 8; ++j) v[j] = act_in[aa[j] + s * 128];

                    ull vp[4];
#pragma unroll
                    for (int j2 = 0; j2 < 4; ++j2) vp[j2] = pk(v[2 * j2], v[2 * j2 + 1]);

#pragma unroll
                    for (int r = 0; r < RO; ++r)
#pragma unroll
                        for (int j2 = 0; j2 < 4; ++j2)
                            ffma2(acc[r][j2], w[r], vp[j2]);
                }
#pragma unroll
                for (int j = 0; j < 8; ++j) aa[j] += 16 * 128;
            }
        }

        // ---- write conv output (+bias), zero slot 0, accumulate LN stats ----
#pragma unroll
        for (int r = 0; r < RO; ++r) {
            const int o = o_base + to * RO + r;
            const float bo = bias[o];
#pragma unroll
            for (int j2 = 0; j2 < 4; ++j2) {
                float x0, x1;
                unpk(acc[r][j2], x0, x1);
                const int p0 = tm * 8 + 2 * j2;
                float y0 = (p0 == 0) ? 0.f : (x0 + bo);
                float y1 = x1 + bo;           // p0+1 is never 0
                act_out[o * 128 + p0]     = y0;
                act_out[o * 128 + p0 + 1] = y1;
                lsum += y0 + y1;
                lsq  += y0 * y0 + y1 * y1;
            }
        }
    }

    // ---- per-tree LayerNorm over all O*128 values (ddof=1 std) ----
#pragma unroll
    for (int off = 16; off; off >>= 1) {
        lsum += __shfl_xor_sync(0xffffffffu, lsum, off);
        lsq  += __shfl_xor_sync(0xffffffffu, lsq,  off);
    }
    const int wid = tid >> 5, lane = tid & 31;
    if (lane == 0) { sm->red[wid] = lsum; sm->red[8 + wid] = lsq; }
    __syncthreads();
    if (tid == 0) {
        float s = 0.f, q = 0.f;
        for (int w = 0; w < 8; ++w) { s += sm->red[w]; q += sm->red[8 + w]; }
        const float n = (float)(O * 128);
        float mean = s / n;
        float var = (q - n * mean * mean) / (n - 1.f);
        var = fmaxf(var, 0.f);
        float inv = 1.f / (sqrtf(var) + 1e-5f);
        sm->red[16] = mean;
        sm->red[17] = inv;
    }
    __syncthreads();
    const float mean = sm->red[16];
    const float inv  = sm->red[17];
    constexpr int E = O * 128 / 256;
    float* pb = act_out + tid * E;
#pragma unroll 4
    for (int i = 0; i < E; ++i) {
        float x = (pb[i] - mean) * inv;
        if (LEAKY && x < 0.f) x *= 0.01f;
        pb[i] = x;
    }
    __syncthreads();
}

// ---------------------------------------------------------------------------
// Weight transpose pre-pass: Wt[(k*C+c)*O + o] = W[o*C*3 + c*3 + k]
// ---------------------------------------------------------------------------
__global__ void wtrans_all(const float* __restrict__ W1,
                           const float* __restrict__ W2,
                           const float* __restrict__ W3)
{
    int i = blockIdx.x * 256 + threadIdx.x;
    if (i < 98304) {                       // W1: O=256, C=128
        const int O = 256, C = 128;
        int o = i % O, t = i / O, c = t % C, k = t / C;
        g_Wt1[i] = W1[(o * C + c) * 3 + k];
    } else if (i < 196608) {               // W2: O=128, C=256
        int j = i - 98304;
        const int O = 128, C = 256;
        int o = j % O, t = j / O, c = t % C, k = t / C;
        g_Wt2[j] = W2[(o * C + c) * 3 + k];
    } else if (i < 221184) {               // W3: O=64, C=128
        int j = i - 196608;
        const int O = 64, C = 128;
        int o = j % O, t = j / O, c = t % C, k = t / C;
        g_Wt3[j] = W3[(o * C + c) * 3 + k];
    }
}

// ---------------------------------------------------------------------------
// Main fused kernel: one CTA per tree.
// ---------------------------------------------------------------------------
__global__ void __launch_bounds__(256, 1)
bao_main(const float* __restrict__ trees,
         const int* __restrict__ indexes,
         const float* __restrict__ b1,
         const float* __restrict__ b2,
         const float* __restrict__ b3,
         const float* __restrict__ W4,
         const float* __restrict__ b4,
         const float* __restrict__ W5,
         const float* __restrict__ b5,
         float* __restrict__ outp)
{
    extern __shared__ char smem_raw[];
    SmemT* sm = (SmemT*)smem_raw;
    const int b = blockIdx.x;
    const int tid = threadIdx.x;

    // load this tree's activations [128][128] into bufB (coalesced float4)
    {
        const float4* src = (const float4*)(trees + (size_t)b * 16384);
        float4* dst = (float4*)sm->bufB;
#pragma unroll
        for (int i = 0; i < 16; ++i) dst[i * 256 + tid] = src[i * 256 + tid];
    }
    // load gather indices (3*127 = 381 ints)
    for (int i = tid; i < 381; i += 256) sm->idx[i] = indexes[(size_t)b * 381 + i];
    __syncthreads();

    // per-thread gather indices for its 8 positions p = tm*8 + j
    const int tm = tid & 15;
    int I[24];
#pragma unroll
    for (int k = 0; k < 3; ++k)
#pragma unroll
        for (int j = 0; j < 8; ++j) {
            int p = tm * 8 + j;
            I[k * 8 + j] = (p == 0) ? 0 : sm->idx[3 * (p - 1) + k];
        }

    layer<128, 256, true >(sm->bufB, sm->bufA, g_Wt1, b1, sm, tid, I);
    layer<256, 128, true >(sm->bufA, sm->bufB, g_Wt2, b2, sm, tid, I);
    layer<128,  64, false>(sm->bufB, sm->bufA, g_Wt3, b3, sm, tid, I);

    // DynamicPooling: max over nodes -> red[0..63]
    if (tid < 64) {
        const float* row = sm->bufA + tid * 128;
        float m = row[0];
#pragma unroll 8
        for (int i = 1; i < 128; ++i) m = fmaxf(m, row[i]);
        sm->red[tid] = m;
    }
    __syncthreads();

    // FC 64->32 (leaky) -> 32->1
    if (tid < 32) {
        float h = b4[tid];
#pragma unroll 8
        for (int j = 0; j < 64; ++j) h += W4[tid * 64 + j] * sm->red[j];
        if (h < 0.f) h *= 0.01f;
        float contrib = W5[tid] * h;
#pragma unroll
        for (int off = 16; off; off >>= 1)
            contrib += __shfl_xor_sync(0xffffffffu, contrib, off);
        if (tid == 0) outp[b] = contrib + b5[0];
    }
}

// ---------------------------------------------------------------------------
// Launch
// ---------------------------------------------------------------------------
extern "C" void kernel_launch(void* const* d_in, const int* in_sizes, int n_in,
                              void* d_out, int out_size)
{
    const float *trees, *W1, *b1, *W2, *b2, *W3, *b3, *W4, *b4, *W5, *b5;
    const int* indexes;

    if (in_sizes[0] == 33554432 && n_in >= 12 && in_sizes[1] == 780288) {
        // setup_inputs dict order: trees, indexes, W1,b1, W2,b2, W3,b3, W4,b4, W5,b5
        trees   = (const float*)d_in[0];
        indexes = (const int*)  d_in[1];
        W1 = (const float*)d_in[2];  b1 = (const float*)d_in[3];
        W2 = (const float*)d_in[4];  b2 = (const float*)d_in[5];
        W3 = (const float*)d_in[6];  b3 = (const float*)d_in[7];
        W4 = (const float*)d_in[8];  b4 = (const float*)d_in[9];
        W5 = (const float*)d_in[10]; b5 = (const float*)d_in[11];
    } else if (in_sizes[0] == 33554432) {
        // reference() arg order: trees, W1,b1, ..., W5,b5, indexes
        trees = (const float*)d_in[0];
        W1 = (const float*)d_in[1];  b1 = (const float*)d_in[2];
        W2 = (const float*)d_in[3];  b2 = (const float*)d_in[4];
        W3 = (const float*)d_in[5];  b3 = (const float*)d_in[6];
        W4 = (const float*)d_in[7];  b4 = (const float*)d_in[8];
        W5 = (const float*)d_in[9];  b5 = (const float*)d_in[10];
        indexes = (const int*)d_in[11];
    } else {
        // alphabetical order: W1..W5, b1..b5, indexes, trees
        W1 = (const float*)d_in[0];  W2 = (const float*)d_in[1];
        W3 = (const float*)d_in[2];  W4 = (const float*)d_in[3];
        W5 = (const float*)d_in[4];
        b1 = (const float*)d_in[5];  b2 = (const float*)d_in[6];
        b3 = (const float*)d_in[7];  b4 = (const float*)d_in[8];
        b5 = (const float*)d_in[9];
        indexes = (const int*)  d_in[10];
        trees   = (const float*)d_in[11];
    }

    // 1) transpose weights into k-major, o-contiguous layout
    wtrans_all<<<(221184 + 255) / 256, 256>>>(W1, W2, W3);

    // 2) fused per-tree pipeline
    const int smem_bytes = (int)sizeof(SmemT);
    cudaFuncSetAttribute(bao_main, cudaFuncAttributeMaxDynamicSharedMemorySize,
                         smem_bytes);
    bao_main<<<2048, 256, smem_bytes>>>(trees, indexes, b1, b2, b3,
                                        W4, b4, W5, b5, (float*)d_out);
}